// round 1
// baseline (speedup 1.0000x reference)
#include <cuda_runtime.h>
#include <cuda_bf16.h>

#define G   500
#define DN  128
#define DE  64
#define DG  128
#define DO  128

// Device scratch (no allocation allowed)
__device__ int   g_noff[G + 1];
__device__ int   g_eoff[G + 1];
__device__ float g_nagg[G * DN];
__device__ float g_eagg[G * DE];

// ---------------------------------------------------------------------------
// Kernel 0: exclusive prefix sums of per-graph lengths -> segment offsets.
// Lengths staged into smem cooperatively so the serial scans run on smem,
// not on dependent DRAM loads. Two independent serial scans on two threads.
// ---------------------------------------------------------------------------
__global__ void scan_kernel(const int* __restrict__ nn, const int* __restrict__ ne) {
    __shared__ int sn[G];
    __shared__ int se[G];
    for (int i = threadIdx.x; i < G; i += blockDim.x) {
        sn[i] = nn[i];
        se[i] = ne[i];
    }
    __syncthreads();
    if (threadIdx.x == 0) {
        int acc = 0;
        g_noff[0] = 0;
        #pragma unroll 4
        for (int i = 0; i < G; i++) { acc += sn[i]; g_noff[i + 1] = acc; }
    } else if (threadIdx.x == 32) {
        int acc = 0;
        g_eoff[0] = 0;
        #pragma unroll 4
        for (int i = 0; i < G; i++) { acc += se[i]; g_eoff[i + 1] = acc; }
    }
}

// ---------------------------------------------------------------------------
// Kernel 1: fused node + edge segment-mean. Blocks [0,500) do node graphs,
// blocks [500,1000) do edge graphs. 512 threads, float4 coalesced loads.
// ---------------------------------------------------------------------------
__global__ __launch_bounds__(512) void agg_kernel(const float4* __restrict__ nf4,
                                                  const float4* __restrict__ ef4) {
    __shared__ float4 red[512];
    const int b   = blockIdx.x;
    const int tid = threadIdx.x;

    if (b < G) {
        // ---- node aggregation: 128 floats = 32 float4 per row ----
        const int lane = tid & 31;   // float4 column
        const int rg   = tid >> 5;   // 0..15 row group
        const int off0 = g_noff[b];
        const int off1 = g_noff[b + 1];
        const int n    = off1 - off0;
        const float4* base = nf4 + (size_t)off0 * 32 + lane;

        float4 acc = make_float4(0.f, 0.f, 0.f, 0.f);
        #pragma unroll 4
        for (int r = rg; r < n; r += 16) {
            float4 v = base[(size_t)r * 32];
            acc.x += v.x; acc.y += v.y; acc.z += v.z; acc.w += v.w;
        }
        red[rg * 32 + lane] = acc;
        __syncthreads();
        #pragma unroll
        for (int s = 8; s >= 1; s >>= 1) {
            if (rg < s) {
                float4 o = red[(rg + s) * 32 + lane];
                float4 m = red[rg * 32 + lane];
                m.x += o.x; m.y += o.y; m.z += o.z; m.w += o.w;
                red[rg * 32 + lane] = m;
            }
            __syncthreads();
        }
        if (rg == 0) {
            const float inv = 1.0f / (float)max(n, 1);
            float4 m = red[lane];
            m.x *= inv; m.y *= inv; m.z *= inv; m.w *= inv;
            reinterpret_cast<float4*>(g_nagg)[b * 32 + lane] = m;
        }
    } else {
        // ---- edge aggregation: 64 floats = 16 float4 per row ----
        const int g    = b - G;
        const int lane = tid & 15;   // float4 column
        const int rg   = tid >> 4;   // 0..31 row group
        const int off0 = g_eoff[g];
        const int off1 = g_eoff[g + 1];
        const int n    = off1 - off0;
        const float4* base = ef4 + (size_t)off0 * 16 + lane;

        float4 acc = make_float4(0.f, 0.f, 0.f, 0.f);
        #pragma unroll 4
        for (int r = rg; r < n; r += 32) {
            float4 v = base[(size_t)r * 16];
            acc.x += v.x; acc.y += v.y; acc.z += v.z; acc.w += v.w;
        }
        red[rg * 16 + lane] = acc;
        __syncthreads();
        #pragma unroll
        for (int s = 16; s >= 1; s >>= 1) {
            if (rg < s) {
                float4 o = red[(rg + s) * 16 + lane];
                float4 m = red[rg * 16 + lane];
                m.x += o.x; m.y += o.y; m.z += o.z; m.w += o.w;
                red[rg * 16 + lane] = m;
            }
            __syncthreads();
        }
        if (rg == 0) {
            const float inv = 1.0f / (float)max(n, 1);
            float4 m = red[lane];
            m.x *= inv; m.y *= inv; m.z *= inv; m.w *= inv;
            reinterpret_cast<float4*>(g_eagg)[g * 16 + lane] = m;
        }
    }
}

// ---------------------------------------------------------------------------
// Kernel 2: out[g][o] = <nagg[g],Wn[o]> + <eagg[g],We[o]> + <gf[g],Wg[o]> + b[o]
// One warp per (g,o) task; coalesced reads of W rows; butterfly reduce.
// 4 graphs per block -> W stays hot in L1.
// ---------------------------------------------------------------------------
__global__ __launch_bounds__(256) void out_kernel(const float* __restrict__ gf,
                                                  const float* __restrict__ Wn,
                                                  const float* __restrict__ We,
                                                  const float* __restrict__ Wg,
                                                  const float* __restrict__ bias,
                                                  float* __restrict__ out) {
    const int warp  = threadIdx.x >> 5;  // 0..7
    const int lane  = threadIdx.x & 31;
    const int gbase = blockIdx.x * 4;

    for (int t = warp; t < 4 * DO; t += 8) {
        const int g = gbase + (t >> 7);
        const int o = t & 127;
        float s = 0.f;

        const float* na = g_nagg + g * DN;
        const float* wn = Wn + o * DN;
        #pragma unroll
        for (int k = 0; k < DN / 32; k++) s += na[lane + 32 * k] * wn[lane + 32 * k];

        const float* ea = g_eagg + g * DE;
        const float* we = We + o * DE;
        #pragma unroll
        for (int k = 0; k < DE / 32; k++) s += ea[lane + 32 * k] * we[lane + 32 * k];

        const float* ga = gf + g * DG;
        const float* wg = Wg + o * DG;
        #pragma unroll
        for (int k = 0; k < DG / 32; k++) s += ga[lane + 32 * k] * wg[lane + 32 * k];

        #pragma unroll
        for (int d = 16; d; d >>= 1) s += __shfl_xor_sync(0xffffffffu, s, d);

        if (lane == 0) out[g * DO + o] = s + bias[o];
    }
}

// ---------------------------------------------------------------------------
extern "C" void kernel_launch(void* const* d_in, const int* in_sizes, int n_in,
                              void* d_out, int out_size) {
    const float*  node_features = (const float*)d_in[0];   // [N, 128]
    const float*  edge_features = (const float*)d_in[1];   // [E, 64]
    const float*  global_feats  = (const float*)d_in[2];   // [G, 128]
    const float*  W_node        = (const float*)d_in[3];   // [128, 128]
    const float*  W_edges       = (const float*)d_in[4];   // [128, 64]
    const float*  W_global      = (const float*)d_in[5];   // [128, 128]
    const float*  bias          = (const float*)d_in[6];   // [128]
    const int*    num_nodes     = (const int*)d_in[7];     // [G]
    const int*    num_edges     = (const int*)d_in[8];     // [G]
    float*        out           = (float*)d_out;           // [G, 128]

    scan_kernel<<<1, 64>>>(num_nodes, num_edges);
    agg_kernel<<<2 * G, 512>>>((const float4*)node_features,
                               (const float4*)edge_features);
    out_kernel<<<(G + 3) / 4, 256>>>(global_feats, W_node, W_edges, W_global,
                                     bias, out);
}